// round 11
// baseline (speedup 1.0000x reference)
#include <cuda_runtime.h>
#include <cuda_fp16.h>

#define NN 100000
#define NE 1600000
#define F_IN 128
#define F_HID 64
#define N_CLS 16

// ---------------- device scratch (static; ~52.8 MB, same footprint as passing R3/R9) ------
__device__ __half2 g_t[NN * 32];      // t buffer A (fp16, 64 vals/row)
__device__ float   g_h[NN * F_HID];   // 25.6MB; first 12.8MB reused as t buffer B (half2)
__device__ float   g_dinv[NN];        // deg^{-1/2} (deg includes self loop)
__device__ int     g_deg[NN];         // in-edge count; zeroed by FINAL agg for next replay
__device__ int     g_off[NN];         // exclusive prefix of g_deg
__device__ int     g_cur[NN];         // bucket cursors (seeded to g_off each call)
__device__ int2    g_epk[NE];         // packed (src, dinv[src] bits) by dst bucket
__device__ int     g_bsum[128];       // scan block sums (98 blocks)

// NOTE: __device__ symbols are referenced ONLY inside device code. Passing them as
// host-side kernel arguments resolves to the host shadow address and, under GB300
// ATS/HMM, silently backs host pages with device memory -> 128MiB guard trip
// (root cause of rounds 4,5,6,8,10 failures).

// ---------------- f32x2 helpers (Blackwell packed fp32 FMA) ----------------
__device__ __forceinline__ void ffma2(unsigned long long& d,
                                      unsigned long long a, unsigned long long b) {
    asm("fma.rn.f32x2 %0, %1, %2, %3;" : "=l"(d) : "l"(a), "l"(b), "l"(d));
}
__device__ __forceinline__ unsigned long long packdup(float a) {
    unsigned long long r;
    asm("mov.b64 %0, {%1, %1};" : "=l"(r) : "f"(a));
    return r;
}
__device__ __forceinline__ float2 unpk64(unsigned long long v) {
    float2 f;
    asm("mov.b64 {%0, %1}, %2;" : "=f"(f.x), "=f"(f.y) : "l"(v));
    return f;
}

// ---------------- CSR build (int4-vectorized: 4 edges/thread, MLP=4) ----------------
__global__ void k_count4(const int* __restrict__ dst) {
    int i = blockIdx.x * blockDim.x + threadIdx.x;
    if (i < NE / 4) {
        int4 d = ((const int4*)dst)[i];
        atomicAdd(&g_deg[d.x], 1);
        atomicAdd(&g_deg[d.y], 1);
        atomicAdd(&g_deg[d.z], 1);
        atomicAdd(&g_deg[d.w], 1);
    }
}

__global__ void k_scan1() {
    __shared__ int sh[1024];
    int i = blockIdx.x * 1024 + threadIdx.x;
    int v = (i < NN) ? g_deg[i] : 0;
    sh[threadIdx.x] = v;
    __syncthreads();
    #pragma unroll
    for (int ofs = 1; ofs < 1024; ofs <<= 1) {
        int t = (threadIdx.x >= ofs) ? sh[threadIdx.x - ofs] : 0;
        __syncthreads();
        sh[threadIdx.x] += t;
        __syncthreads();
    }
    if (i < NN) g_off[i] = sh[threadIdx.x] - v;              // exclusive within block
    if (threadIdx.x == 1023) g_bsum[blockIdx.x] = sh[1023];  // block total
}

// fused: every block re-scans the 98 block sums, then finalizes off/cur/dinv.
__global__ void k_scan23_dinv(int nb) {
    __shared__ int pref[128];
    __shared__ int wt[4];
    int t = threadIdx.x;
    if (t < 128) {
        int lane = t & 31, w = t >> 5;
        int v = (t < nb) ? g_bsum[t] : 0;
        int xr = v;
        #pragma unroll
        for (int o = 1; o < 32; o <<= 1) {
            int y = __shfl_up_sync(0xffffffffu, xr, o);
            if (lane >= o) xr += y;
        }
        if (lane == 31) wt[w] = xr;          // inclusive warp totals
        pref[t] = xr - v;                    // exclusive within warp
    }
    __syncthreads();
    if (t < 128) {
        int w = t >> 5;
        int add = 0;
        #pragma unroll
        for (int k = 0; k < 4; k++) if (k < w) add += wt[k];
        pref[t] += add;                      // exclusive prefix of bsum
    }
    __syncthreads();
    int i = blockIdx.x * blockDim.x + t;
    if (i < NN) {
        int off = g_off[i] + pref[i >> 10];
        g_off[i] = off;
        g_cur[i] = off;
        g_dinv[i] = rsqrtf((float)(g_deg[i] + 1));   // +1 self loop; always > 0
    }
}

__global__ void k_fill4(const int* __restrict__ src, const int* __restrict__ dst) {
    int i = blockIdx.x * blockDim.x + threadIdx.x;
    if (i < NE / 4) {
        int4 d = ((const int4*)dst)[i];
        int4 s = ((const int4*)src)[i];
        int p0 = atomicAdd(&g_cur[d.x], 1);
        int p1 = atomicAdd(&g_cur[d.y], 1);
        int p2 = atomicAdd(&g_cur[d.z], 1);
        int p3 = atomicAdd(&g_cur[d.w], 1);
        g_epk[p0] = make_int2(s.x, __float_as_int(g_dinv[s.x]));
        g_epk[p1] = make_int2(s.y, __float_as_int(g_dinv[s.y]));
        g_epk[p2] = make_int2(s.z, __float_as_int(g_dinv[s.z]));
        g_epk[p3] = make_int2(s.w, __float_as_int(g_dinv[s.w]));
    }
}

// ---------------- GEMM layer 0: g_t[n,64](fp16) = x[n,128] @ W0, FFMA2 (verbatim-pass) ----
template<int K>
__global__ __launch_bounds__(256, 2) void k_gemm64(const float* __restrict__ A,
                                                   const float* __restrict__ W) {
    const int KC = 16;
    const int XS_STRIDE = 260;
    __shared__ float Xs[KC * XS_STRIDE];
    __shared__ float Ws[KC * 64];

    int tid = threadIdx.x;
    int tx = tid & 7;
    int ty = tid >> 3;
    int nb = blockIdx.x * 256;

    unsigned long long accp[8][4];
    #pragma unroll
    for (int i = 0; i < 8; i++)
        #pragma unroll
        for (int j = 0; j < 4; j++) accp[i][j] = 0ull;

    for (int k0 = 0; k0 < K; k0 += KC) {
        {
            int kk = (tid & 3) * 4;
            #pragma unroll
            for (int r = 0; r < 4; r++) {
                int node = r * 64 + (tid >> 2);
                float4 v = make_float4(0.f, 0.f, 0.f, 0.f);
                int gn = nb + node;
                if (gn < NN) v = *(const float4*)(A + (long)gn * K + k0 + kk);
                Xs[(kk + 0) * XS_STRIDE + node] = v.x;
                Xs[(kk + 1) * XS_STRIDE + node] = v.y;
                Xs[(kk + 2) * XS_STRIDE + node] = v.z;
                Xs[(kk + 3) * XS_STRIDE + node] = v.w;
            }
            int kk2 = tid >> 4;
            int c = (tid & 15) * 4;
            *(float4*)(Ws + kk2 * 64 + c) = *(const float4*)(W + (k0 + kk2) * 64 + c);
        }
        __syncthreads();

        #pragma unroll
        for (int kk = 0; kk < KC; kk++) {
            float4 a0 = *(const float4*)(Xs + kk * XS_STRIDE + ty * 8);
            float4 a1 = *(const float4*)(Xs + kk * XS_STRIDE + ty * 8 + 4);
            ulonglong2 w0 = *(const ulonglong2*)(Ws + kk * 64 + tx * 8);
            ulonglong2 w1 = *(const ulonglong2*)(Ws + kk * 64 + tx * 8 + 4);
            unsigned long long bp[4] = {w0.x, w0.y, w1.x, w1.y};
            float a[8] = {a0.x, a0.y, a0.z, a0.w, a1.x, a1.y, a1.z, a1.w};
            #pragma unroll
            for (int i = 0; i < 8; i++) {
                unsigned long long ad = packdup(a[i]);
                #pragma unroll
                for (int j = 0; j < 4; j++)
                    ffma2(accp[i][j], ad, bp[j]);
            }
        }
        __syncthreads();
    }

    #pragma unroll
    for (int i = 0; i < 8; i++) {
        int gn = nb + ty * 8 + i;
        if (gn < NN) {
            __half2 hh[4];
            #pragma unroll
            for (int j = 0; j < 4; j++) {
                float2 f = unpk64(accp[i][j]);
                hh[j] = __floats2half2_rn(f.x, f.y);
            }
            *(uint4*)(g_t + (long)gn * 32 + tx * 4) = *(uint4*)hh;
        }
    }
}

// ---------------- Fused aggregation (+ next-layer matvec OR classifier) ----------------
// DIR=0: tin=g_t, tout=g_h-as-half2.  DIR=1: tin=g_h-as-half2, tout=g_t.
// Buffers resolved in DEVICE code (never passed from host).
// FINAL=0: h=relu(agg+bias); block-cooperative t_next = h @ Wn -> tout.
// FINAL=1: classifier out = h @ Wc + bc; resets g_deg for next graph replay.
template<int FINAL, int DIR>
__global__ __launch_bounds__(256) void k_aggw(const float* __restrict__ bias,
                                              const float* __restrict__ Wn,
                                              const float* __restrict__ bc,
                                              float* __restrict__ out) {
    const __half2* __restrict__ tin = DIR ? (const __half2*)g_h : g_t;
    __half2* __restrict__ tout      = DIR ? g_t : (__half2*)g_h;

    __shared__ __align__(16) float Wsh[FINAL ? (F_HID * N_CLS) : (F_HID * F_HID)];
    __shared__ __align__(16) float hs[8 * 66];   // stride 66: conflict-free matvec reads
    __shared__ int2 se[8][32];

    const int NWELE = FINAL ? (F_HID * N_CLS) : (F_HID * F_HID);
    for (int i = threadIdx.x; i < NWELE; i += 256) Wsh[i] = Wn[i];
    __syncthreads();

    int w    = threadIdx.x >> 5;
    int lane = threadIdx.x & 31;
    float2 bv = ((const float2*)bias)[lane];

    for (int grp = blockIdx.x; grp < NN / 8; grp += gridDim.x) {
        int node = grp * 8 + w;
        int row = g_off[node];
        int cnt = g_deg[node];
        if (FINAL && lane == 0) g_deg[node] = 0;   // self-reset for next replay

        float2 a0 = make_float2(0.f, 0.f), a1 = make_float2(0.f, 0.f);
        for (int base = 0; base < cnt; base += 32) {
            int idx = base + lane;
            if (idx < cnt) se[w][lane] = g_epk[row + idx];
            __syncwarp();
            int m = min(32, cnt - base);
            if (m == 32) {
                #pragma unroll
                for (int j = 0; j < 32; j += 2) {
                    int2 e0 = se[w][j];
                    int2 e1 = se[w][j + 1];
                    float2 t0 = __half22float2(tin[(long)e0.x * 32 + lane]);
                    float2 t1 = __half22float2(tin[(long)e1.x * 32 + lane]);
                    a0.x = fmaf(__int_as_float(e0.y), t0.x, a0.x);
                    a0.y = fmaf(__int_as_float(e0.y), t0.y, a0.y);
                    a1.x = fmaf(__int_as_float(e1.y), t1.x, a1.x);
                    a1.y = fmaf(__int_as_float(e1.y), t1.y, a1.y);
                }
            } else {
                #pragma unroll 4
                for (int j = 0; j < m; j++) {
                    int2 ev = se[w][j];
                    float2 tv = __half22float2(tin[(long)ev.x * 32 + lane]);
                    a0.x = fmaf(__int_as_float(ev.y), tv.x, a0.x);
                    a0.y = fmaf(__int_as_float(ev.y), tv.y, a0.y);
                }
            }
            __syncwarp();
        }

        float  di = g_dinv[node];
        float2 ts = __half22float2(tin[(long)node * 32 + lane]);
        float ox = (a0.x + a1.x + di * ts.x) * di + bv.x;
        float oy = (a0.y + a1.y + di * ts.y) * di + bv.y;
        if (!FINAL) { ox = fmaxf(ox, 0.f); oy = fmaxf(oy, 0.f); }
        *(float2*)(hs + w * 66 + 2 * lane) = make_float2(ox, oy);
        __syncthreads();

        if (!FINAL) {
            // block matvec: warp w -> cols [w*8, w*8+8); lane: node n=lane>>2, pair lane&3
            int n   = lane >> 2;
            int col = w * 8 + (lane & 3) * 2;
            unsigned long long c0 = 0ull, c1 = 0ull;
            #pragma unroll
            for (int k = 0; k < F_HID; k += 2) {
                ffma2(c0, packdup(hs[n * 66 + k]),
                      *(const unsigned long long*)(Wsh + k * 64 + col));
                ffma2(c1, packdup(hs[n * 66 + k + 1]),
                      *(const unsigned long long*)(Wsh + (k + 1) * 64 + col));
            }
            float2 f0 = unpk64(c0), f1 = unpk64(c1);
            int onode = grp * 8 + n;
            tout[(long)onode * 32 + w * 4 + (lane & 3)] =
                __floats2half2_rn(f0.x + f1.x, f0.y + f1.y);
        } else {
            int c  = lane & 15;
            int k0 = (lane >> 4) * 32;
            float s = 0.f;
            #pragma unroll
            for (int k = 0; k < 32; k++)
                s = fmaf(hs[w * 66 + k0 + k], Wsh[(k0 + k) * N_CLS + c], s);
            s += __shfl_xor_sync(0xffffffffu, s, 16);
            if (lane < 16) out[(long)node * N_CLS + c] = s + __ldg(bc + c);
        }
        __syncthreads();   // protect hs across groups
    }
}

// ---------------- launch (host passes ONLY harness pointers) ----------------
extern "C" void kernel_launch(void* const* d_in, const int* in_sizes, int n_in,
                              void* d_out, int out_size) {
    (void)in_sizes; (void)n_in; (void)out_size;
    const float* x  = (const float*)d_in[0];
    const int*   ei = (const int*)d_in[1];
    const float* W0 = (const float*)d_in[2];
    const float* b0 = (const float*)d_in[3];
    const float* W1 = (const float*)d_in[4];
    const float* b1 = (const float*)d_in[5];
    const float* W2 = (const float*)d_in[6];
    const float* b2 = (const float*)d_in[7];
    const float* Wc = (const float*)d_in[8];
    const float* bc = (const float*)d_in[9];
    float* out = (float*)d_out;

    const int* src = ei;            // edge_index[0]
    const int* dst = ei + NE;       // edge_index[1]

    int nbE4 = (NE / 4 + 255) / 256;   // 1563
    int nbS  = (NN + 1023) / 1024;     // 98
    int nbN  = (NN + 255) / 256;       // 391
    int nbG  = (NN + 255) / 256;       // 391
    int nbW  = 1184;                   // 8 * 148: grid-stride agg blocks

    // CSR build + normalization (g_deg enters zeroed: BSS on first call,
    // FINAL agg's self-reset on every subsequent replay)
    k_count4<<<nbE4, 256>>>(dst);
    k_scan1<<<nbS, 1024>>>();
    k_scan23_dinv<<<nbN, 256>>>(nbS);
    k_fill4<<<nbE4, 256>>>(src, dst);

    // layer 0 GEMM: t0 = x @ W0 -> g_t
    k_gemm64<F_IN><<<nbG, 256>>>(x, W0);
    // agg(t0)+relu, fused t1 = h @ W1 -> buffer B
    k_aggw<0, 0><<<nbW, 256>>>(b0, W1, nullptr, nullptr);
    // agg(t1)+relu, fused t2 = h @ W2 -> g_t
    k_aggw<0, 1><<<nbW, 256>>>(b1, W2, nullptr, nullptr);
    // agg(t2) + classifier -> out   (+ g_deg reset)
    k_aggw<1, 0><<<nbW, 256>>>(b2, Wc, bc, out);
}

// round 12
// speedup vs baseline: 1.1690x; 1.1690x over previous
#include <cuda_runtime.h>
#include <cuda_fp16.h>

#define NN 100000
#define NE 1600000
#define F_IN 128
#define F_HID 64
#define N_CLS 16

// ---------------- device scratch (static; ~52.8 MB, same footprint as passing rounds) ------
__device__ __half2 g_t[NN * 32];      // t = act @ W (gather source, fp16, 64 vals/row)
__device__ float   g_h[NN * F_HID];   // aggregated activations (fp32)
__device__ float   g_dinv[NN];        // deg^{-1/2} (deg includes self loop)
__device__ int     g_deg[NN];         // in-edge count; zeroed by FINAL agg for next replay
__device__ int     g_off[NN];         // exclusive prefix of g_deg
__device__ int     g_cur[NN];         // bucket cursors (seeded to g_off each call)
__device__ int2    g_epk[NE];         // packed (src, dinv[src] bits) by dst bucket
__device__ int     g_bsum[128];       // scan block sums (98 blocks)

// RULE (root cause of R4/5/6/8/10 guard trips): __device__ symbols are referenced ONLY
// inside device code — never passed as host-side kernel arguments (host shadow address
// + GB300 ATS would silently back host pages with device memory -> 128MiB guard trip).

// ---------------- CSR build (int4-vectorized: 4 edges/thread, MLP=4) ----------------
__global__ void k_count4(const int* __restrict__ dst) {
    int i = blockIdx.x * blockDim.x + threadIdx.x;
    if (i < NE / 4) {
        int4 d = ((const int4*)dst)[i];
        atomicAdd(&g_deg[d.x], 1);
        atomicAdd(&g_deg[d.y], 1);
        atomicAdd(&g_deg[d.z], 1);
        atomicAdd(&g_deg[d.w], 1);
    }
}

__global__ void k_scan1() {
    __shared__ int sh[1024];
    int i = blockIdx.x * 1024 + threadIdx.x;
    int v = (i < NN) ? g_deg[i] : 0;
    sh[threadIdx.x] = v;
    __syncthreads();
    #pragma unroll
    for (int ofs = 1; ofs < 1024; ofs <<= 1) {
        int t = (threadIdx.x >= ofs) ? sh[threadIdx.x - ofs] : 0;
        __syncthreads();
        sh[threadIdx.x] += t;
        __syncthreads();
    }
    if (i < NN) g_off[i] = sh[threadIdx.x] - v;              // exclusive within block
    if (threadIdx.x == 1023) g_bsum[blockIdx.x] = sh[1023];  // block total
}

// fused: every block re-scans the 98 block sums, then finalizes off/cur/dinv.
__global__ void k_scan23_dinv(int nb) {
    __shared__ int pref[128];
    __shared__ int wt[4];
    int t = threadIdx.x;
    if (t < 128) {
        int lane = t & 31, w = t >> 5;
        int v = (t < nb) ? g_bsum[t] : 0;
        int xr = v;
        #pragma unroll
        for (int o = 1; o < 32; o <<= 1) {
            int y = __shfl_up_sync(0xffffffffu, xr, o);
            if (lane >= o) xr += y;
        }
        if (lane == 31) wt[w] = xr;          // inclusive warp totals
        pref[t] = xr - v;                    // exclusive within warp
    }
    __syncthreads();
    if (t < 128) {
        int w = t >> 5;
        int add = 0;
        #pragma unroll
        for (int k = 0; k < 4; k++) if (k < w) add += wt[k];
        pref[t] += add;                      // exclusive prefix of bsum
    }
    __syncthreads();
    int i = blockIdx.x * blockDim.x + t;
    if (i < NN) {
        int off = g_off[i] + pref[i >> 10];
        g_off[i] = off;
        g_cur[i] = off;
        g_dinv[i] = rsqrtf((float)(g_deg[i] + 1));   // +1 self loop; always > 0
    }
}

__global__ void k_fill4(const int* __restrict__ src, const int* __restrict__ dst) {
    int i = blockIdx.x * blockDim.x + threadIdx.x;
    if (i < NE / 4) {
        int4 d = ((const int4*)dst)[i];
        int4 s = ((const int4*)src)[i];
        int p0 = atomicAdd(&g_cur[d.x], 1);
        int p1 = atomicAdd(&g_cur[d.y], 1);
        int p2 = atomicAdd(&g_cur[d.z], 1);
        int p3 = atomicAdd(&g_cur[d.w], 1);
        g_epk[p0] = make_int2(s.x, __float_as_int(g_dinv[s.x]));
        g_epk[p1] = make_int2(s.y, __float_as_int(g_dinv[s.y]));
        g_epk[p2] = make_int2(s.z, __float_as_int(g_dinv[s.z]));
        g_epk[p3] = make_int2(s.w, __float_as_int(g_dinv[s.w]));
    }
}

// ---------------- GEMM via HMMA: g_t[n,64](fp16) = A[n,K](fp32) @ W[K,64](fp32) ----------
// Block: 128-node x 64-col tile, 8 warps; warp = 16 nodes x 64 cols (8 m16n8k16 n-tiles).
// USE_GH selects A = g_h IN DEVICE CODE (never host-passed). A staged fp32->fp16 with
// named scalars. smem stride 40 halfs -> frag loads hit 32 distinct banks ((20g+t2)%32).
template<int K, int USE_GH>
__global__ __launch_bounds__(256) void k_gemmh(const float* __restrict__ Aext,
                                               const float* __restrict__ Wg) {
    const float* __restrict__ A = USE_GH ? (const float*)g_h : Aext;

    __shared__ __half As[128 * 40];
    __shared__ __half Ws[64 * 40];

    int tid  = threadIdx.x;
    int w    = tid >> 5;
    int lane = tid & 31;
    int g    = lane >> 2;    // 0..7
    int t2   = lane & 3;     // 0..3
    int nb   = blockIdx.x * 128;

    float acc[8][4];
    #pragma unroll
    for (int nt = 0; nt < 8; nt++)
        #pragma unroll
        for (int r = 0; r < 4; r++) acc[nt][r] = 0.f;

    for (int k0 = 0; k0 < K; k0 += 32) {
        // stage A chunk: 2 threads per row, 16 floats -> 8 half2 (named scalars only)
        {
            int row  = tid >> 1;
            int hoff = (tid & 1) * 16;
            int gn = nb + row;
            __half2 h0, h1, h2, h3, h4, h5, h6, h7;
            if (gn < NN) {
                const float4* p = (const float4*)(A + (long)gn * K + k0 + hoff);
                float4 f0 = p[0], f1 = p[1], f2 = p[2], f3 = p[3];
                h0 = __floats2half2_rn(f0.x, f0.y);
                h1 = __floats2half2_rn(f0.z, f0.w);
                h2 = __floats2half2_rn(f1.x, f1.y);
                h3 = __floats2half2_rn(f1.z, f1.w);
                h4 = __floats2half2_rn(f2.x, f2.y);
                h5 = __floats2half2_rn(f2.z, f2.w);
                h6 = __floats2half2_rn(f3.x, f3.y);
                h7 = __floats2half2_rn(f3.z, f3.w);
            } else {
                h0 = h1 = h2 = h3 = h4 = h5 = h6 = h7 = __floats2half2_rn(0.f, 0.f);
            }
            __half2* ar = (__half2*)(As + row * 40 + hoff);
            ar[0] = h0; ar[1] = h1; ar[2] = h2; ar[3] = h3;
            ar[4] = h4; ar[5] = h5; ar[6] = h6; ar[7] = h7;
            // stage W chunk transposed: Ws[c][kk]
            #pragma unroll
            for (int i = 0; i < 8; i++) {
                int idx = tid * 8 + i;
                int kk = idx >> 6, c = idx & 63;
                Ws[c * 40 + kk] = __float2half(Wg[(k0 + kk) * 64 + c]);
            }
        }
        __syncthreads();

        #pragma unroll
        for (int ks = 0; ks < 2; ks++) {
            const __half* ap = As + (w * 16 + g) * 40 + ks * 16 + t2 * 2;
            unsigned a0 = *(const unsigned*)ap;                 // (row g,   k 2*t2)
            unsigned a1 = *(const unsigned*)(ap + 8 * 40);      // (row g+8, k 2*t2)
            unsigned a2 = *(const unsigned*)(ap + 8);           // (row g,   k 2*t2+8)
            unsigned a3 = *(const unsigned*)(ap + 8 * 40 + 8);  // (row g+8, k 2*t2+8)
            #pragma unroll
            for (int nt = 0; nt < 8; nt++) {
                const __half* bp = Ws + (nt * 8 + g) * 40 + ks * 16 + t2 * 2;
                unsigned b0 = *(const unsigned*)bp;             // (col nt*8+g, k 2*t2)
                unsigned b1 = *(const unsigned*)(bp + 8);       // (col nt*8+g, k 2*t2+8)
                asm("mma.sync.aligned.m16n8k16.row.col.f32.f16.f16.f32 "
                    "{%0,%1,%2,%3}, {%4,%5,%6,%7}, {%8,%9}, {%0,%1,%2,%3};"
                    : "+f"(acc[nt][0]), "+f"(acc[nt][1]),
                      "+f"(acc[nt][2]), "+f"(acc[nt][3])
                    : "r"(a0), "r"(a1), "r"(a2), "r"(a3), "r"(b0), "r"(b1));
            }
        }
        __syncthreads();
    }

    // epilogue: c0,c1 -> (node g,   cols 2*(nt*4+t2)..+1); c2,c3 -> node g+8
    int node0 = nb + w * 16 + g;
    #pragma unroll
    for (int nt = 0; nt < 8; nt++) {
        if (node0 < NN)
            g_t[(long)node0 * 32 + nt * 4 + t2] = __floats2half2_rn(acc[nt][0], acc[nt][1]);
        if (node0 + 8 < NN)
            g_t[(long)(node0 + 8) * 32 + nt * 4 + t2] = __floats2half2_rn(acc[nt][2], acc[nt][3]);
    }
}

// ---------------- Aggregation: warp per node (independent), smem edge broadcast ----------
// h[node] = act( bias + dinv_i * ( sum_s dinv_s * t[s] + dinv_i * t[node] ) )
// FINAL: fused classifier out = h @ Wc + bc; resets g_deg for next graph replay
template<int RELU, int FINAL>
__global__ __launch_bounds__(256) void k_agg(const float* __restrict__ bias,
                                             const float* __restrict__ Wc,
                                             const float* __restrict__ bc,
                                             float* __restrict__ out) {
    __shared__ float Wcs[F_HID * N_CLS];
    __shared__ float hs[8][F_HID];
    __shared__ int2  se[8][32];
    if (FINAL) {
        for (int i = threadIdx.x; i < F_HID * N_CLS; i += 256) Wcs[i] = Wc[i];
        __syncthreads();
    }

    int w    = threadIdx.x >> 5;
    int lane = threadIdx.x & 31;
    int node = blockIdx.x * 8 + w;      // grid exact: NN/8 blocks

    const __half2* __restrict__ tp = g_t;
    float2 a0 = make_float2(0.f, 0.f), a1 = make_float2(0.f, 0.f);

    int row = g_off[node];
    int cnt = g_deg[node];
    if (FINAL && lane == 0) g_deg[node] = 0;   // self-reset for next replay

    for (int base = 0; base < cnt; base += 32) {
        int idx = base + lane;
        if (idx < cnt) se[w][lane] = g_epk[row + idx];
        __syncwarp();
        int m = min(32, cnt - base);
        if (m == 32) {
            #pragma unroll
            for (int j = 0; j < 32; j += 2) {
                int2 e0 = se[w][j];
                int2 e1 = se[w][j + 1];
                float2 t0 = __half22float2(tp[(long)e0.x * 32 + lane]);
                float2 t1 = __half22float2(tp[(long)e1.x * 32 + lane]);
                a0.x = fmaf(__int_as_float(e0.y), t0.x, a0.x);
                a0.y = fmaf(__int_as_float(e0.y), t0.y, a0.y);
                a1.x = fmaf(__int_as_float(e1.y), t1.x, a1.x);
                a1.y = fmaf(__int_as_float(e1.y), t1.y, a1.y);
            }
        } else {
            #pragma unroll 4
            for (int j = 0; j < m; j++) {
                int2 ev = se[w][j];
                float2 tv = __half22float2(tp[(long)ev.x * 32 + lane]);
                a0.x = fmaf(__int_as_float(ev.y), tv.x, a0.x);
                a0.y = fmaf(__int_as_float(ev.y), tv.y, a0.y);
            }
        }
        __syncwarp();
    }

    float  di = g_dinv[node];
    float2 ts = __half22float2(tp[(long)node * 32 + lane]);
    float2 bv = ((const float2*)bias)[lane];
    float ox = (a0.x + a1.x + di * ts.x) * di + bv.x;
    float oy = (a0.y + a1.y + di * ts.y) * di + bv.y;

    if (FINAL) {
        hs[w][2 * lane]     = ox;
        hs[w][2 * lane + 1] = oy;
        __syncwarp();
        int c  = lane & 15;
        int k0 = (lane >> 4) * 32;
        float s = 0.f;
        #pragma unroll
        for (int k = 0; k < 32; k++)
            s = fmaf(hs[w][k0 + k], Wcs[(k0 + k) * N_CLS + c], s);
        s += __shfl_xor_sync(0xffffffffu, s, 16);
        if (lane < 16) out[(long)node * N_CLS + c] = s + __ldg(bc + c);
    } else {
        if (RELU) { ox = fmaxf(ox, 0.f); oy = fmaxf(oy, 0.f); }
        ((float2*)g_h)[(long)node * 32 + lane] = make_float2(ox, oy);
    }
}

// ---------------- launch (host passes ONLY harness pointers) ----------------
extern "C" void kernel_launch(void* const* d_in, const int* in_sizes, int n_in,
                              void* d_out, int out_size) {
    (void)in_sizes; (void)n_in; (void)out_size;
    const float* x  = (const float*)d_in[0];
    const int*   ei = (const int*)d_in[1];
    const float* W0 = (const float*)d_in[2];
    const float* b0 = (const float*)d_in[3];
    const float* W1 = (const float*)d_in[4];
    const float* b1 = (const float*)d_in[5];
    const float* W2 = (const float*)d_in[6];
    const float* b2 = (const float*)d_in[7];
    const float* Wc = (const float*)d_in[8];
    const float* bc = (const float*)d_in[9];
    float* out = (float*)d_out;

    const int* src = ei;            // edge_index[0]
    const int* dst = ei + NE;       // edge_index[1]

    int nbE4 = (NE / 4 + 255) / 256;   // 1563
    int nbS  = (NN + 1023) / 1024;     // 98
    int nbN  = (NN + 255) / 256;       // 391
    int nbG  = (NN + 127) / 128;       // 782
    int nbA  = NN / 8;                 // 12500 (exact)

    // CSR build + normalization (g_deg enters zeroed: BSS on first call,
    // FINAL agg's self-reset on every subsequent replay)
    k_count4<<<nbE4, 256>>>(dst);
    k_scan1<<<nbS, 1024>>>();
    k_scan23_dinv<<<nbN, 256>>>(nbS);
    k_fill4<<<nbE4, 256>>>(src, dst);

    // layer 0: t0 = x @ W0 -> g_t (HMMA)
    k_gemmh<F_IN, 0><<<nbG, 256>>>(x, W0);
    k_agg<1, 0><<<nbA, 256>>>(b0, nullptr, nullptr, nullptr);
    // layer 1: t1 = h @ W1 (A = g_h resolved in device code)
    k_gemmh<F_HID, 1><<<nbG, 256>>>(nullptr, W1);
    k_agg<1, 0><<<nbA, 256>>>(b1, nullptr, nullptr, nullptr);
    // layer 2 + fused classifier (+ g_deg reset)
    k_gemmh<F_HID, 1><<<nbG, 256>>>(nullptr, W2);
    k_agg<0, 1><<<nbA, 256>>>(b2, Wc, bc, out);
}

// round 13
// speedup vs baseline: 1.3643x; 1.1671x over previous
#include <cuda_runtime.h>
#include <cuda_fp16.h>

#define NN 100000
#define NE 1600000
#define F_IN 128
#define F_HID 64
#define N_CLS 16

// ---------------- device scratch (static; ~46 MB) ----------------
__device__ __half2 g_t[NN * 32];      // t' = dinv*(act @ W)  (gather source, fp16)
__device__ float   g_h[NN * F_HID];   // aggregated activations (fp32)
__device__ float   g_dinv[NN];        // deg^{-1/2} (deg includes self loop)
__device__ int     g_deg[NN];         // in-edge count; zeroed by FINAL agg for next replay
__device__ int     g_off[NN];         // exclusive prefix of g_deg
__device__ int     g_cur[NN];         // bucket cursors (seeded to g_off each call)
__device__ int     g_src[NE];         // src index by dst bucket (dinv premultiplied in g_t)
__device__ int     g_bsum[128];       // scan block sums (98 blocks)

// RULE (root cause of R4/5/6/8/10 guard trips): __device__ symbols are referenced ONLY
// inside device code — never passed as host-side kernel arguments.

// ---------------- CSR build ----------------
__global__ void k_count4(const int* __restrict__ dst) {
    int i = blockIdx.x * blockDim.x + threadIdx.x;
    if (i < NE / 4) {
        int4 d = ((const int4*)dst)[i];
        atomicAdd(&g_deg[d.x], 1);
        atomicAdd(&g_deg[d.y], 1);
        atomicAdd(&g_deg[d.z], 1);
        atomicAdd(&g_deg[d.w], 1);
    }
}

// warp-shuffle block scan (1024 threads, 2 barriers)
__global__ void k_scan1() {
    __shared__ int wt[32];
    int i = blockIdx.x * 1024 + threadIdx.x;
    int lane = threadIdx.x & 31, w = threadIdx.x >> 5;
    int v = (i < NN) ? g_deg[i] : 0;
    int x = v;
    #pragma unroll
    for (int o = 1; o < 32; o <<= 1) {
        int y = __shfl_up_sync(0xffffffffu, x, o);
        if (lane >= o) x += y;
    }
    if (lane == 31) wt[w] = x;               // inclusive warp totals
    __syncthreads();
    if (w == 0) {                            // scan the 32 warp totals
        int a = wt[lane];
        int s = a;
        #pragma unroll
        for (int o = 1; o < 32; o <<= 1) {
            int y = __shfl_up_sync(0xffffffffu, s, o);
            if (lane >= o) s += y;
        }
        wt[lane] = s - a;                    // exclusive warp offsets
        if (lane == 31) g_bsum[blockIdx.x] = s;   // block total
    }
    __syncthreads();
    if (i < NN) g_off[i] = x - v + wt[w];    // exclusive within block
}

// fused: every block re-scans the 98 block sums, then finalizes off/cur/dinv.
__global__ void k_scan23_dinv(int nb) {
    __shared__ int pref[128];
    __shared__ int wt[4];
    int t = threadIdx.x;
    if (t < 128) {
        int lane = t & 31, w = t >> 5;
        int v = (t < nb) ? g_bsum[t] : 0;
        int xr = v;
        #pragma unroll
        for (int o = 1; o < 32; o <<= 1) {
            int y = __shfl_up_sync(0xffffffffu, xr, o);
            if (lane >= o) xr += y;
        }
        if (lane == 31) wt[w] = xr;
        pref[t] = xr - v;
    }
    __syncthreads();
    if (t < 128) {
        int w = t >> 5;
        int add = 0;
        #pragma unroll
        for (int k = 0; k < 4; k++) if (k < w) add += wt[k];
        pref[t] += add;
    }
    __syncthreads();
    int i = blockIdx.x * blockDim.x + t;
    if (i < NN) {
        int off = g_off[i] + pref[i >> 10];
        g_off[i] = off;
        g_cur[i] = off;
        g_dinv[i] = rsqrtf((float)(g_deg[i] + 1));   // +1 self loop; always > 0
    }
}

// fill: only src index (4 B) — no dinv gather (premultiplied into g_t)
__global__ void k_fill4(const int* __restrict__ src, const int* __restrict__ dst) {
    int i = blockIdx.x * blockDim.x + threadIdx.x;
    if (i < NE / 4) {
        int4 d = ((const int4*)dst)[i];
        int4 s = ((const int4*)src)[i];
        int p0 = atomicAdd(&g_cur[d.x], 1);
        int p1 = atomicAdd(&g_cur[d.y], 1);
        int p2 = atomicAdd(&g_cur[d.z], 1);
        int p3 = atomicAdd(&g_cur[d.w], 1);
        g_src[p0] = s.x;
        g_src[p1] = s.y;
        g_src[p2] = s.z;
        g_src[p3] = s.w;
    }
}

// ---------------- GEMM via HMMA: g_t[n] = dinv[n] * (A[n,:] @ W) in fp16 ----------------
// Block: 128-node x 64-col tile, 8 warps; warp = 16 nodes x 64 cols (8 m16n8k16 n-tiles).
template<int K, int USE_GH>
__global__ __launch_bounds__(256) void k_gemmh(const float* __restrict__ Aext,
                                               const float* __restrict__ Wg) {
    const float* __restrict__ A = USE_GH ? (const float*)g_h : Aext;

    __shared__ __half As[128 * 40];
    __shared__ __half Ws[64 * 40];

    int tid  = threadIdx.x;
    int w    = tid >> 5;
    int lane = tid & 31;
    int g    = lane >> 2;    // 0..7
    int t2   = lane & 3;     // 0..3
    int nb   = blockIdx.x * 128;

    float acc[8][4];
    #pragma unroll
    for (int nt = 0; nt < 8; nt++)
        #pragma unroll
        for (int r = 0; r < 4; r++) acc[nt][r] = 0.f;

    for (int k0 = 0; k0 < K; k0 += 32) {
        {
            int row  = tid >> 1;
            int hoff = (tid & 1) * 16;
            int gn = nb + row;
            __half2 h0, h1, h2, h3, h4, h5, h6, h7;
            if (gn < NN) {
                const float4* p = (const float4*)(A + (long)gn * K + k0 + hoff);
                float4 f0 = p[0], f1 = p[1], f2 = p[2], f3 = p[3];
                h0 = __floats2half2_rn(f0.x, f0.y);
                h1 = __floats2half2_rn(f0.z, f0.w);
                h2 = __floats2half2_rn(f1.x, f1.y);
                h3 = __floats2half2_rn(f1.z, f1.w);
                h4 = __floats2half2_rn(f2.x, f2.y);
                h5 = __floats2half2_rn(f2.z, f2.w);
                h6 = __floats2half2_rn(f3.x, f3.y);
                h7 = __floats2half2_rn(f3.z, f3.w);
            } else {
                h0 = h1 = h2 = h3 = h4 = h5 = h6 = h7 = __floats2half2_rn(0.f, 0.f);
            }
            __half2* ar = (__half2*)(As + row * 40 + hoff);
            ar[0] = h0; ar[1] = h1; ar[2] = h2; ar[3] = h3;
            ar[4] = h4; ar[5] = h5; ar[6] = h6; ar[7] = h7;
            #pragma unroll
            for (int i = 0; i < 8; i++) {
                int idx = tid * 8 + i;
                int kk = idx >> 6, c = idx & 63;
                Ws[c * 40 + kk] = __float2half(Wg[(k0 + kk) * 64 + c]);
            }
        }
        __syncthreads();

        #pragma unroll
        for (int ks = 0; ks < 2; ks++) {
            const __half* ap = As + (w * 16 + g) * 40 + ks * 16 + t2 * 2;
            unsigned a0 = *(const unsigned*)ap;
            unsigned a1 = *(const unsigned*)(ap + 8 * 40);
            unsigned a2 = *(const unsigned*)(ap + 8);
            unsigned a3 = *(const unsigned*)(ap + 8 * 40 + 8);
            #pragma unroll
            for (int nt = 0; nt < 8; nt++) {
                const __half* bp = Ws + (nt * 8 + g) * 40 + ks * 16 + t2 * 2;
                unsigned b0 = *(const unsigned*)bp;
                unsigned b1 = *(const unsigned*)(bp + 8);
                asm("mma.sync.aligned.m16n8k16.row.col.f32.f16.f16.f32 "
                    "{%0,%1,%2,%3}, {%4,%5,%6,%7}, {%8,%9}, {%0,%1,%2,%3};"
                    : "+f"(acc[nt][0]), "+f"(acc[nt][1]),
                      "+f"(acc[nt][2]), "+f"(acc[nt][3])
                    : "r"(a0), "r"(a1), "r"(a2), "r"(a3), "r"(b0), "r"(b1));
            }
        }
        __syncthreads();
    }

    // epilogue with dinv premultiply: c0,c1 -> node g; c2,c3 -> node g+8
    int node0 = nb + w * 16 + g;
    float d0 = (node0 < NN)     ? g_dinv[node0]     : 0.f;
    float d1 = (node0 + 8 < NN) ? g_dinv[node0 + 8] : 0.f;
    #pragma unroll
    for (int nt = 0; nt < 8; nt++) {
        if (node0 < NN)
            g_t[(long)node0 * 32 + nt * 4 + t2] =
                __floats2half2_rn(acc[nt][0] * d0, acc[nt][1] * d0);
        if (node0 + 8 < NN)
            g_t[(long)(node0 + 8) * 32 + nt * 4 + t2] =
                __floats2half2_rn(acc[nt][2] * d1, acc[nt][3] * d1);
    }
}

// ---------------- Aggregation: warp per node, half-warp dual-edge gather ----------------
// acc lanes: hl=lane&15 holds cols [4hl..4hl+3]; side=lane>>4 handles edges j+side.
// h = (Sum t'[s] + t'[i]) * dinv_i + bias;   t' already has dinv premultiplied.
// FINAL: fused classifier out = h @ Wc + bc; resets g_deg for next graph replay.
template<int RELU, int FINAL>
__global__ __launch_bounds__(256) void k_agg(const float* __restrict__ bias,
                                             const float* __restrict__ Wc,
                                             const float* __restrict__ bc,
                                             float* __restrict__ out) {
    __shared__ float Wcs[F_HID * N_CLS];
    __shared__ float hs[8][F_HID];
    __shared__ int   se[8][32];
    if (FINAL) {
        for (int i = threadIdx.x; i < F_HID * N_CLS; i += 256) Wcs[i] = Wc[i];
        __syncthreads();
    }

    int w    = threadIdx.x >> 5;
    int lane = threadIdx.x & 31;
    int hl   = lane & 15;
    int side = lane >> 4;
    float smask = side ? 0.f : 1.f;     // tail-edge mask for high half
    int node = blockIdx.x * 8 + w;      // grid exact: NN/8 blocks

    const __half2* __restrict__ tp = g_t;
    float4 acc = make_float4(0.f, 0.f, 0.f, 0.f);

    int row = g_off[node];
    int cnt = g_deg[node];
    if (FINAL && lane == 0) g_deg[node] = 0;   // self-reset for next replay

    for (int base = 0; base < cnt; base += 32) {
        int idx = base + lane;
        if (idx < cnt) se[w][lane] = g_src[row + idx];
        __syncwarp();
        int m = min(32, cnt - base);
        int mfull = m & ~1;
        if (m == 32) {
            #pragma unroll
            for (int j = 0; j < 32; j += 2) {
                int e = se[w][j + side];
                uint2 v = *(const uint2*)(tp + (long)e * 32 + hl * 2);
                float2 f0 = __half22float2(*(__half2*)&v.x);
                float2 f1 = __half22float2(*(__half2*)&v.y);
                acc.x += f0.x; acc.y += f0.y; acc.z += f1.x; acc.w += f1.y;
            }
        } else {
            #pragma unroll 2
            for (int j = 0; j < mfull; j += 2) {
                int e = se[w][j + side];
                uint2 v = *(const uint2*)(tp + (long)e * 32 + hl * 2);
                float2 f0 = __half22float2(*(__half2*)&v.x);
                float2 f1 = __half22float2(*(__half2*)&v.y);
                acc.x += f0.x; acc.y += f0.y; acc.z += f1.x; acc.w += f1.y;
            }
            if (m & 1) {                       // odd tail: low half only (masked FMA)
                int e = se[w][m - 1];
                uint2 v = *(const uint2*)(tp + (long)e * 32 + hl * 2);
                float2 f0 = __half22float2(*(__half2*)&v.x);
                float2 f1 = __half22float2(*(__half2*)&v.y);
                acc.x = fmaf(smask, f0.x, acc.x);
                acc.y = fmaf(smask, f0.y, acc.y);
                acc.z = fmaf(smask, f1.x, acc.z);
                acc.w = fmaf(smask, f1.y, acc.w);
            }
        }
        __syncwarp();
    }

    // combine the two half-warps (same cols, disjoint edge subsets)
    acc.x += __shfl_xor_sync(0xffffffffu, acc.x, 16);
    acc.y += __shfl_xor_sync(0xffffffffu, acc.y, 16);
    acc.z += __shfl_xor_sync(0xffffffffu, acc.z, 16);
    acc.w += __shfl_xor_sync(0xffffffffu, acc.w, 16);

    // self term t'[node] + scale + bias
    float di = g_dinv[node];
    uint2 sv = *(const uint2*)(tp + (long)node * 32 + hl * 2);
    float2 s0 = __half22float2(*(__half2*)&sv.x);
    float2 s1 = __half22float2(*(__half2*)&sv.y);
    const float4 bv = *(const float4*)(bias + hl * 4);
    float o0 = (acc.x + s0.x) * di + bv.x;
    float o1 = (acc.y + s0.y) * di + bv.y;
    float o2 = (acc.z + s1.x) * di + bv.z;
    float o3 = (acc.w + s1.y) * di + bv.w;

    if (FINAL) {
        if (side == 0) *(float4*)(hs[w] + hl * 4) = make_float4(o0, o1, o2, o3);
        __syncwarp();
        int c  = lane & 15;
        int k0 = (lane >> 4) * 32;
        float s = 0.f;
        #pragma unroll
        for (int k = 0; k < 32; k++)
            s = fmaf(hs[w][k0 + k], Wcs[(k0 + k) * N_CLS + c], s);
        s += __shfl_xor_sync(0xffffffffu, s, 16);
        if (lane < 16) out[(long)node * N_CLS + c] = s + __ldg(bc + c);
    } else {
        if (RELU) {
            o0 = fmaxf(o0, 0.f); o1 = fmaxf(o1, 0.f);
            o2 = fmaxf(o2, 0.f); o3 = fmaxf(o3, 0.f);
        }
        if (side == 0)
            *(float4*)(g_h + (long)node * 64 + hl * 4) = make_float4(o0, o1, o2, o3);
    }
}

// ---------------- launch (host passes ONLY harness pointers) ----------------
extern "C" void kernel_launch(void* const* d_in, const int* in_sizes, int n_in,
                              void* d_out, int out_size) {
    (void)in_sizes; (void)n_in; (void)out_size;
    const float* x  = (const float*)d_in[0];
    const int*   ei = (const int*)d_in[1];
    const float* W0 = (const float*)d_in[2];
    const float* b0 = (const float*)d_in[3];
    const float* W1 = (const float*)d_in[4];
    const float* b1 = (const float*)d_in[5];
    const float* W2 = (const float*)d_in[6];
    const float* b2 = (const float*)d_in[7];
    const float* Wc = (const float*)d_in[8];
    const float* bc = (const float*)d_in[9];
    float* out = (float*)d_out;

    const int* src = ei;            // edge_index[0]
    const int* dst = ei + NE;       // edge_index[1]

    int nbE4 = (NE / 4 + 255) / 256;   // 1563
    int nbS  = (NN + 1023) / 1024;     // 98
    int nbN  = (NN + 255) / 256;       // 391
    int nbG  = (NN + 127) / 128;       // 782
    int nbA  = NN / 8;                 // 12500 (exact)

    // CSR build + normalization (g_deg enters zeroed: BSS on first call,
    // FINAL agg's self-reset on every subsequent replay)
    k_count4<<<nbE4, 256>>>(dst);
    k_scan1<<<nbS, 1024>>>();
    k_scan23_dinv<<<nbN, 256>>>(nbS);
    k_fill4<<<nbE4, 256>>>(src, dst);

    // layer 0: t0' = dinv * (x @ W0) -> g_t (HMMA)
    k_gemmh<F_IN, 0><<<nbG, 256>>>(x, W0);
    k_agg<1, 0><<<nbA, 256>>>(b0, nullptr, nullptr, nullptr);
    // layer 1
    k_gemmh<F_HID, 1><<<nbG, 256>>>(nullptr, W1);
    k_agg<1, 0><<<nbA, 256>>>(b1, nullptr, nullptr, nullptr);
    // layer 2 + fused classifier (+ g_deg reset)
    k_gemmh<F_HID, 1><<<nbG, 256>>>(nullptr, W2);
    k_agg<0, 1><<<nbA, 256>>>(b2, Wc, bc, out);
}